// round 11
// baseline (speedup 1.0000x reference)
#include <cuda_runtime.h>
#include <cuda_fp16.h>
#include <cstdint>

#define NN 200000
#define NE 800000

// ---------------- device scratch (no allocations allowed) ----------------
__device__ int g_is64;
__device__ int g_mask_mode;  // 0 = byte bool, 1 = int32, 2 = int64
__device__ unsigned int g_flags[3];
__device__ int g_count[NN];
__device__ int g_off[NN + 1];
__device__ int g_cur[NN];
__device__ int g_bsum[256];
__device__ int g_boff[256];
__device__ unsigned int g_sorted[2 * NE];
__device__ __half g_Bthi[64 * 512];  // basesT fp16 (n-major, k-contig)

// ---------------- helpers ----------------
__device__ __forceinline__ int ldidx(const int* p, int i, int is64) {
    return is64 ? p[2 * i] : p[i];
}
__device__ __forceinline__ uint32_t smem_u32(const void* p) {
    uint32_t a;
    asm("{ .reg .u64 t; cvta.to.shared.u64 t, %1; cvt.u32.u64 %0, t; }"
        : "=r"(a) : "l"(p));
    return a;
}
__device__ __forceinline__ void ldsm4(uint32_t* r, uint32_t addr) {
    asm volatile("ldmatrix.sync.aligned.m8n8.x4.shared.b16 {%0,%1,%2,%3}, [%4];"
                 : "=r"(r[0]), "=r"(r[1]), "=r"(r[2]), "=r"(r[3]) : "r"(addr));
}
__device__ __forceinline__ void mma16816(float* c, const uint32_t* a,
                                         const uint32_t* b) {
    asm volatile(
        "mma.sync.aligned.m16n8k16.row.col.f32.f16.f16.f32 "
        "{%0,%1,%2,%3}, {%4,%5,%6,%7}, {%8,%9}, {%0,%1,%2,%3};"
        : "+f"(c[0]), "+f"(c[1]), "+f"(c[2]), "+f"(c[3])
        : "r"(a[0]), "r"(a[1]), "r"(a[2]), "r"(a[3]), "r"(b[0]), "r"(b[1]));
}

// ---------------- K0a: zero hist + flags ----------------
__global__ void zero_kernel(int N) {
    int i0 = blockIdx.x * blockDim.x + threadIdx.x;
    if (i0 < 3) g_flags[i0] = 0u;
    for (int i = i0; i < N; i += gridDim.x * blockDim.x) g_count[i] = 0;
}

// ---------------- K0b: parallel dtype sniff ----------------
__global__ void sniff_kernel(const unsigned int* idx_words, int n_idx_words,
                             const unsigned int* mask_words, int n_mask) {
    int i0 = blockIdx.x * blockDim.x + threadIdx.x;
    int stride = gridDim.x * blockDim.x;
    unsigned f0 = 0, f1 = 0, f2 = 0;
    for (int i = 1 + 2 * i0; i < n_idx_words; i += 2 * stride)
        f0 |= (idx_words[i] != 0u);
    for (int i = i0; i < n_mask / 4; i += stride)
        f1 |= (mask_words[i] > 1u);
    for (int i = 1 + 2 * i0; i < n_mask / 2; i += 2 * stride)
        f2 |= (mask_words[i] != 0u);
    if (f0) atomicOr(&g_flags[0], 1u);
    if (f1) atomicOr(&g_flags[1], 1u);
    if (f2) atomicOr(&g_flags[2], 1u);
}

__global__ void finalize_sniff_kernel() {
    g_is64 = g_flags[0] ? 0 : 1;
    g_mask_mode = g_flags[1] ? 0 : (g_flags[2] ? 1 : 2);
}

// ---------------- prep: basesT to fp16 ----------------
__global__ void prep_bases_kernel(const float* __restrict__ bases) {
    for (int idx = blockIdx.x * blockDim.x + threadIdx.x; idx < 512 * 64;
         idx += gridDim.x * blockDim.x) {
        int n = idx >> 9, k = idx & 511;
        g_Bthi[n * 512 + k] = __float2half(bases[k * 64 + n]);
    }
}

// ---------------- K2: histogram of edge-direction targets ----------------
__global__ void hist_kernel(const int* src, const int* tgt, int E) {
    int is64 = g_is64;
    for (int i = blockIdx.x * blockDim.x + threadIdx.x; i < 2 * E;
         i += gridDim.x * blockDim.x) {
        int t = (i < E) ? ldidx(tgt, i, is64) : ldidx(src, i - E, is64);
        atomicAdd(&g_count[t], 1);
    }
}

// ---------------- K3: multi-block exclusive scan ----------------
__global__ void scan1_kernel(int N) {
    __shared__ int red[256];
    int b = blockIdx.x, t = threadIdx.x;
    int base = b * 1024 + t * 4;
    int s = 0;
#pragma unroll
    for (int j = 0; j < 4; j++) {
        int idx = base + j;
        if (idx < N) s += g_count[idx];
    }
    red[t] = s;
    __syncthreads();
    for (int off = 128; off > 0; off >>= 1) {
        if (t < off) red[t] += red[t + off];
        __syncthreads();
    }
    if (t == 0) g_bsum[b] = red[0];
}

__global__ void scan2_kernel(int nb, int N) {
    __shared__ int ts[256];
    int t = threadIdx.x;
    int v = (t < nb) ? g_bsum[t] : 0;
    ts[t] = v;
    __syncthreads();
    for (int off = 1; off < 256; off <<= 1) {
        int u = (t >= off) ? ts[t - off] : 0;
        __syncthreads();
        ts[t] += u;
        __syncthreads();
    }
    if (t < nb) g_boff[t] = ts[t] - v;
    if (t == 255) g_off[N] = ts[255];
}

__global__ void scan3_kernel(int N) {
    __shared__ int ts[256];
    int b = blockIdx.x, t = threadIdx.x;
    int base = b * 1024 + t * 4;
    int c[4];
    int s = 0;
#pragma unroll
    for (int j = 0; j < 4; j++) {
        int idx = base + j;
        c[j] = (idx < N) ? g_count[idx] : 0;
        s += c[j];
    }
    ts[t] = s;
    __syncthreads();
    for (int off = 1; off < 256; off <<= 1) {
        int u = (t >= off) ? ts[t - off] : 0;
        __syncthreads();
        ts[t] += u;
        __syncthreads();
    }
    int run = ts[t] - s + g_boff[b];
#pragma unroll
    for (int j = 0; j < 4; j++) {
        int idx = base + j;
        if (idx < N) {
            g_off[idx] = run;
            g_cur[idx] = run;
            run += c[j];
        }
    }
}

// ---------------- K4: scatter edges sorted by target ----------------
__global__ void scatter_kernel(const int* src, const int* tgt, const int* et,
                               int E) {
    int is64 = g_is64;
    for (int i = blockIdx.x * blockDim.x + threadIdx.x; i < 2 * E;
         i += gridDim.x * blockDim.x) {
        int e = (i < E) ? i : i - E;
        int s, t;
        if (i < E) { s = ldidx(src, e, is64); t = ldidx(tgt, e, is64); }
        else       { s = ldidx(tgt, e, is64); t = ldidx(src, e, is64); }
        int r = ldidx(et, e, is64);
        int pos = atomicAdd(&g_cur[t], 1);
        g_sorted[pos] = ((unsigned int)s << 4) | (unsigned int)r;
    }
}

// ---------------- K5: FUSED aggregation + tensor-core GEMM ----------------
// CTA: 128 nodes, 512 threads (16 warps), 1 CTA/SM.
// Phase A: warp w aggregates nodes [w*8, w*8+8) in fp32, writes fp16 to
//          smem A[128][520] (stride 1040 B; 1040 mod 128 = 16 -> ldmatrix
//          conflict-free).
// Phase B: out(128x64) = A @ BT^T via mma.sync fp16, warp grid 4(m) x 4(n),
//          each warp 32 rows x 16 cols. A and B fully smem-resident.
#define OFF_ATT 0
#define OFF_B   1024
#define OFF_A   (1024 + 64 * 1040)
#define SMEM_FU (OFF_A + 128 * 1040)

__global__ __launch_bounds__(512, 1) void fused_kernel(
    const float* __restrict__ x, const void* __restrict__ mask,
    const float* __restrict__ att, float* __restrict__ out, int N) {
    extern __shared__ __align__(16) char sm[];
    uint32_t sbase = smem_u32(sm);
    float4* att_s = (float4*)(sm + OFF_ATT);
    int tid = threadIdx.x, wid = tid >> 5, lid = tid & 31;
    int nb = blockIdx.x * 128;

    if (tid < 34) att_s[tid] = ((const float4*)att)[tid];

    // ---- stage B: 64 rows x 1024 B ----
#pragma unroll
    for (int t = 0; t < 4; t++) {
        int idx = t * 512 + tid;
        int row = idx >> 5;
        int cb = (idx & 31) * 32;
        *(uint4*)(sm + OFF_B + row * 1040 + cb) =
            *(const uint4*)((const char*)g_Bthi + row * 1024 + cb);
        *(uint4*)(sm + OFF_B + row * 1040 + cb + 16) =
            *(const uint4*)((const char*)g_Bthi + row * 1024 + cb + 16);
    }
    __syncthreads();

    // ---- Phase A: aggregate 8 nodes per warp ----
    int mm = g_mask_mode;
#pragma unroll 1
    for (int j = 0; j < 8; j++) {
        int nl = wid * 8 + j;
        int n = nb + nl;
        if (n >= N) break;
        float acc0[8], acc1[8];
#pragma unroll
        for (int b = 0; b < 8; b++) { acc0[b] = 0.f; acc1[b] = 0.f; }

        int beg = g_off[n], end = g_off[n + 1];
        int i = beg;
#pragma unroll 1
        for (; i + 3 < end; i += 4) {
            unsigned int p0 = g_sorted[i], p1 = g_sorted[i + 1];
            unsigned int p2 = g_sorted[i + 2], p3 = g_sorted[i + 3];
            const float* s0 = x + (size_t)(p0 >> 4) * 64;
            const float* s1 = x + (size_t)(p1 >> 4) * 64;
            const float* s2 = x + (size_t)(p2 >> 4) * 64;
            const float* s3 = x + (size_t)(p3 >> 4) * 64;
            float x0a = s0[lid], x0b = s0[32 + lid];
            float x1a = s1[lid], x1b = s1[32 + lid];
            float x2a = s2[lid], x2b = s2[32 + lid];
            float x3a = s3[lid], x3b = s3[32 + lid];
            float a0[8], a1[8], a2[8], a3[8];
            *(float4*)&a0[0] = att_s[(p0 & 15u) * 2];
            *(float4*)&a0[4] = att_s[(p0 & 15u) * 2 + 1];
            *(float4*)&a1[0] = att_s[(p1 & 15u) * 2];
            *(float4*)&a1[4] = att_s[(p1 & 15u) * 2 + 1];
            *(float4*)&a2[0] = att_s[(p2 & 15u) * 2];
            *(float4*)&a2[4] = att_s[(p2 & 15u) * 2 + 1];
            *(float4*)&a3[0] = att_s[(p3 & 15u) * 2];
            *(float4*)&a3[4] = att_s[(p3 & 15u) * 2 + 1];
#pragma unroll
            for (int b = 0; b < 8; b++) {
                acc0[b] += a0[b] * x0a + a1[b] * x1a + a2[b] * x2a + a3[b] * x3a;
                acc1[b] += a0[b] * x0b + a1[b] * x1b + a2[b] * x2b + a3[b] * x3b;
            }
        }
#pragma unroll 1
        for (; i < end; i++) {
            unsigned int p = g_sorted[i];
            const float* s = x + (size_t)(p >> 4) * 64;
            float xa = s[lid], xb = s[32 + lid];
            float ar[8];
            *(float4*)&ar[0] = att_s[(p & 15u) * 2];
            *(float4*)&ar[4] = att_s[(p & 15u) * 2 + 1];
#pragma unroll
            for (int b = 0; b < 8; b++) {
                acc0[b] += ar[b] * xa;
                acc1[b] += ar[b] * xb;
            }
        }
        int keep;
        if (mm == 0)      keep = ((const unsigned char*)mask)[n];
        else if (mm == 1) keep = ((const int*)mask)[n];
        else              keep = ((const int*)mask)[2 * n];
        if (keep) {
            const float* s = x + (size_t)n * 64;
            float xa = s[lid], xb = s[32 + lid];
            float ar[8];
            *(float4*)&ar[0] = att_s[32];
            *(float4*)&ar[4] = att_s[33];
#pragma unroll
            for (int b = 0; b < 8; b++) {
                acc0[b] += ar[b] * xa;
                acc1[b] += ar[b] * xb;
            }
        }
        // write fp16 row nl: k = b*64 + lane and b*64 + 32 + lane
        char* arow = sm + OFF_A + nl * 1040;
#pragma unroll
        for (int b = 0; b < 8; b++) {
            ((__half*)(arow + b * 128))[lid] = __float2half(acc0[b]);
            ((__half*)(arow + b * 128 + 64))[lid] = __float2half(acc1[b]);
        }
    }
    __syncthreads();

    // ---- Phase B: GEMM from smem ----
    int warp_m = (wid & 3) * 32;
    int warp_n = (wid >> 2) * 16;

    float acc[2][2][4];
#pragma unroll
    for (int mt = 0; mt < 2; mt++)
#pragma unroll
        for (int nt = 0; nt < 2; nt++)
#pragma unroll
            for (int q = 0; q < 4; q++) acc[mt][nt][q] = 0.f;

    uint32_t a_addr = sbase + OFF_A + (uint32_t)(warp_m + (lid & 15)) * 1040 +
                      (uint32_t)(lid & 16);
    uint32_t b_addr = sbase + OFF_B +
                      (uint32_t)(warp_n + (lid & 7) + ((lid >> 4) & 1) * 8) * 1040 +
                      (uint32_t)(((lid >> 3) & 1) * 16);

#pragma unroll 4
    for (int kk = 0; kk < 32; kk++) {
        uint32_t kb = (uint32_t)(kk * 32);
        uint32_t af[2][4], bf[4];
        ldsm4(af[0], a_addr + kb);
        ldsm4(af[1], a_addr + 16 * 1040 + kb);
        ldsm4(bf, b_addr + kb);
#pragma unroll
        for (int mt = 0; mt < 2; mt++) {
            mma16816(acc[mt][0], af[mt], &bf[0]);
            mma16816(acc[mt][1], af[mt], &bf[2]);
        }
    }

    // ---- store ----
    int trow = lid >> 2, tcol = (lid & 3) * 2;
#pragma unroll
    for (int mt = 0; mt < 2; mt++) {
        int m0 = nb + warp_m + mt * 16 + trow;
#pragma unroll
        for (int nt = 0; nt < 2; nt++) {
            int col = warp_n + nt * 8 + tcol;
            if (m0 < N)
                *(float2*)(out + (size_t)m0 * 64 + col) =
                    make_float2(acc[mt][nt][0], acc[mt][nt][1]);
            if (m0 + 8 < N)
                *(float2*)(out + (size_t)(m0 + 8) * 64 + col) =
                    make_float2(acc[mt][nt][2], acc[mt][nt][3]);
        }
    }
}

// ---------------- launch ----------------
extern "C" void kernel_launch(void* const* d_in, const int* in_sizes, int n_in,
                              void* d_out, int out_size) {
    const float* x = (const float*)d_in[0];
    const void* mask = d_in[1];
    const int* src = (const int*)d_in[2];
    const int* tgt = (const int*)d_in[3];
    const int* et = (const int*)d_in[4];
    const float* bases = (const float*)d_in[5];
    const float* att = (const float*)d_in[6];
    float* out = (float*)d_out;

    int N = in_sizes[1];
    int E = in_sizes[2];
    int nb = (N + 1023) / 1024;

    cudaFuncSetAttribute(fused_kernel,
                         cudaFuncAttributeMaxDynamicSharedMemorySize, SMEM_FU);

    zero_kernel<<<256, 256>>>(N);
    sniff_kernel<<<256, 256>>>((const unsigned int*)d_in[2], E,
                               (const unsigned int*)d_in[1], N);
    finalize_sniff_kernel<<<1, 1>>>();
    prep_bases_kernel<<<128, 256>>>(bases);
    hist_kernel<<<3200, 256>>>(src, tgt, E);
    scan1_kernel<<<nb, 256>>>(N);
    scan2_kernel<<<1, 256>>>(nb, N);
    scan3_kernel<<<nb, 256>>>(N);
    scatter_kernel<<<3200, 256>>>(src, tgt, et, E);
    fused_kernel<<<(N + 127) / 128, 512, SMEM_FU>>>(x, mask, att, out, N);
}

// round 12
// speedup vs baseline: 1.1444x; 1.1444x over previous
#include <cuda_runtime.h>
#include <cuda_fp16.h>
#include <cstdint>

#define NN 200000
#define NE 800000
#define NPAD 200064   // 1563 * 128

// ---------------- device scratch (no allocations allowed) ----------------
__device__ unsigned int g_flags[3];   // zero-init; OR-monotone, replay-safe
__device__ int g_count[NN];
__device__ int g_off[NN + 1];
__device__ int g_cur[NN];
__device__ int g_bsum[256];
__device__ int g_boff[256];
__device__ unsigned int g_sorted[2 * NE];
__device__ __half g_Ahi[(size_t)NPAD * 512];  // 205 MB
__device__ __half g_Bthi[64 * 512];           // basesT fp16 (n-major, k-contig)

// ---------------- helpers ----------------
__device__ __forceinline__ int ldidx(const int* p, int i, int is64) {
    return is64 ? p[2 * i] : p[i];
}
__device__ __forceinline__ uint32_t smem_u32(const void* p) {
    uint32_t a;
    asm("{ .reg .u64 t; cvta.to.shared.u64 t, %1; cvt.u32.u64 %0, t; }"
        : "=r"(a) : "l"(p));
    return a;
}
__device__ __forceinline__ void ldsm4(uint32_t* r, uint32_t addr) {
    asm volatile("ldmatrix.sync.aligned.m8n8.x4.shared.b16 {%0,%1,%2,%3}, [%4];"
                 : "=r"(r[0]), "=r"(r[1]), "=r"(r[2]), "=r"(r[3]) : "r"(addr));
}
__device__ __forceinline__ void mma16816(float* c, const uint32_t* a,
                                         const uint32_t* b) {
    asm volatile(
        "mma.sync.aligned.m16n8k16.row.col.f32.f16.f16.f32 "
        "{%0,%1,%2,%3}, {%4,%5,%6,%7}, {%8,%9}, {%0,%1,%2,%3};"
        : "+f"(c[0]), "+f"(c[1]), "+f"(c[2]), "+f"(c[3])
        : "r"(a[0]), "r"(a[1]), "r"(a[2]), "r"(a[3]), "r"(b[0]), "r"(b[1]));
}
__device__ __forceinline__ void cp16(uint32_t saddr, const void* gptr) {
    asm volatile("cp.async.cg.shared.global [%0], [%1], 16;"
                 :: "r"(saddr), "l"(gptr) : "memory");
}
#define CP_COMMIT() asm volatile("cp.async.commit_group;" ::: "memory")
#define CP_WAIT(n)  asm volatile("cp.async.wait_group %0;" :: "n"(n) : "memory")

// ---------------- K0a: zero hist (flags are OR-monotone, never re-zeroed) --
__global__ void zero_kernel(int N) {
    int i0 = blockIdx.x * blockDim.x + threadIdx.x;
    for (int i = i0; i < N; i += gridDim.x * blockDim.x) g_count[i] = 0;
}

// ---------------- K0b: parallel dtype sniff ----------------
__global__ void sniff_kernel(const unsigned int* idx_words, int n_idx_words,
                             const unsigned int* mask_words, int n_mask) {
    int i0 = blockIdx.x * blockDim.x + threadIdx.x;
    int stride = gridDim.x * blockDim.x;
    unsigned f0 = 0, f1 = 0, f2 = 0;
    for (int i = 1 + 2 * i0; i < n_idx_words; i += 2 * stride)
        f0 |= (idx_words[i] != 0u);
    for (int i = i0; i < n_mask / 4; i += stride)
        f1 |= (mask_words[i] > 1u);
    for (int i = 1 + 2 * i0; i < n_mask / 2; i += 2 * stride)
        f2 |= (mask_words[i] != 0u);
    if (f0) atomicOr(&g_flags[0], 1u);
    if (f1) atomicOr(&g_flags[1], 1u);
    if (f2) atomicOr(&g_flags[2], 1u);
}

// ---------------- prep: basesT to fp16 ----------------
__global__ void prep_bases_kernel(const float* __restrict__ bases) {
    for (int idx = blockIdx.x * blockDim.x + threadIdx.x; idx < 512 * 64;
         idx += gridDim.x * blockDim.x) {
        int n = idx >> 9, k = idx & 511;
        g_Bthi[n * 512 + k] = __float2half(bases[k * 64 + n]);
    }
}

// ---------------- K2: histogram of edge-direction targets ----------------
__global__ void hist_kernel(const int* src, const int* tgt, int E) {
    int is64 = g_flags[0] ? 0 : 1;
    for (int i = blockIdx.x * blockDim.x + threadIdx.x; i < 2 * E;
         i += gridDim.x * blockDim.x) {
        int t = (i < E) ? ldidx(tgt, i, is64) : ldidx(src, i - E, is64);
        atomicAdd(&g_count[t], 1);
    }
}

// ---------------- K3: multi-block exclusive scan ----------------
__global__ void scan1_kernel(int N) {
    __shared__ int red[256];
    int b = blockIdx.x, t = threadIdx.x;
    int base = b * 1024 + t * 4;
    int s = 0;
#pragma unroll
    for (int j = 0; j < 4; j++) {
        int idx = base + j;
        if (idx < N) s += g_count[idx];
    }
    red[t] = s;
    __syncthreads();
    for (int off = 128; off > 0; off >>= 1) {
        if (t < off) red[t] += red[t + off];
        __syncthreads();
    }
    if (t == 0) g_bsum[b] = red[0];
}

__global__ void scan2_kernel(int nb, int N) {
    __shared__ int ts[256];
    int t = threadIdx.x;
    int v = (t < nb) ? g_bsum[t] : 0;
    ts[t] = v;
    __syncthreads();
    for (int off = 1; off < 256; off <<= 1) {
        int u = (t >= off) ? ts[t - off] : 0;
        __syncthreads();
        ts[t] += u;
        __syncthreads();
    }
    if (t < nb) g_boff[t] = ts[t] - v;
    if (t == 255) g_off[N] = ts[255];
}

__global__ void scan3_kernel(int N) {
    __shared__ int ts[256];
    int b = blockIdx.x, t = threadIdx.x;
    int base = b * 1024 + t * 4;
    int c[4];
    int s = 0;
#pragma unroll
    for (int j = 0; j < 4; j++) {
        int idx = base + j;
        c[j] = (idx < N) ? g_count[idx] : 0;
        s += c[j];
    }
    ts[t] = s;
    __syncthreads();
    for (int off = 1; off < 256; off <<= 1) {
        int u = (t >= off) ? ts[t - off] : 0;
        __syncthreads();
        ts[t] += u;
        __syncthreads();
    }
    int run = ts[t] - s + g_boff[b];
#pragma unroll
    for (int j = 0; j < 4; j++) {
        int idx = base + j;
        if (idx < N) {
            g_off[idx] = run;
            g_cur[idx] = run;
            run += c[j];
        }
    }
}

// ---------------- K4: scatter edges sorted by target ----------------
__global__ void scatter_kernel(const int* src, const int* tgt, const int* et,
                               int E) {
    int is64 = g_flags[0] ? 0 : 1;
    for (int i = blockIdx.x * blockDim.x + threadIdx.x; i < 2 * E;
         i += gridDim.x * blockDim.x) {
        int e = (i < E) ? i : i - E;
        int s, t;
        if (i < E) { s = ldidx(src, e, is64); t = ldidx(tgt, e, is64); }
        else       { s = ldidx(tgt, e, is64); t = ldidx(src, e, is64); }
        int r = ldidx(et, e, is64);
        int pos = atomicAdd(&g_cur[t], 1);
        g_sorted[pos] = ((unsigned int)s << 4) | (unsigned int)r;
    }
}

// ---------------- K5: aggregation, warp per node, float2 gathers, x4 MLP ----
// Lane owns dims (2*lane, 2*lane+1): ONE LDG.64 per edge, 4 in flight.
__global__ void agg_kernel(const float* __restrict__ x,
                           const void* __restrict__ mask,
                           const float* __restrict__ att, int N) {
    __shared__ __align__(16) float4 att_s[34];
    int tid = threadIdx.x;
    if (tid < 34) att_s[tid] = ((const float4*)att)[tid];
    __syncthreads();

    int warp = tid >> 5, lane = tid & 31;
    int n = blockIdx.x * 8 + warp;
    if (n >= N) return;

    float ax[8], ay[8];
#pragma unroll
    for (int b = 0; b < 8; b++) { ax[b] = 0.f; ay[b] = 0.f; }

    int beg = g_off[n], end = g_off[n + 1];
    int i = beg;
#pragma unroll 1
    for (; i + 3 < end; i += 4) {
        unsigned int p0 = g_sorted[i], p1 = g_sorted[i + 1];
        unsigned int p2 = g_sorted[i + 2], p3 = g_sorted[i + 3];
        float2 x0 = *(const float2*)(x + (size_t)(p0 >> 4) * 64 + 2 * lane);
        float2 x1 = *(const float2*)(x + (size_t)(p1 >> 4) * 64 + 2 * lane);
        float2 x2 = *(const float2*)(x + (size_t)(p2 >> 4) * 64 + 2 * lane);
        float2 x3 = *(const float2*)(x + (size_t)(p3 >> 4) * 64 + 2 * lane);
        float a0[8], a1[8], a2[8], a3[8];
        *(float4*)&a0[0] = att_s[(p0 & 15u) * 2];
        *(float4*)&a0[4] = att_s[(p0 & 15u) * 2 + 1];
        *(float4*)&a1[0] = att_s[(p1 & 15u) * 2];
        *(float4*)&a1[4] = att_s[(p1 & 15u) * 2 + 1];
        *(float4*)&a2[0] = att_s[(p2 & 15u) * 2];
        *(float4*)&a2[4] = att_s[(p2 & 15u) * 2 + 1];
        *(float4*)&a3[0] = att_s[(p3 & 15u) * 2];
        *(float4*)&a3[4] = att_s[(p3 & 15u) * 2 + 1];
#pragma unroll
        for (int b = 0; b < 8; b++) {
            ax[b] += a0[b] * x0.x + a1[b] * x1.x + a2[b] * x2.x + a3[b] * x3.x;
            ay[b] += a0[b] * x0.y + a1[b] * x1.y + a2[b] * x2.y + a3[b] * x3.y;
        }
    }
#pragma unroll 1
    for (; i < end; i++) {
        unsigned int p = g_sorted[i];
        float2 xv = *(const float2*)(x + (size_t)(p >> 4) * 64 + 2 * lane);
        float ar[8];
        *(float4*)&ar[0] = att_s[(p & 15u) * 2];
        *(float4*)&ar[4] = att_s[(p & 15u) * 2 + 1];
#pragma unroll
        for (int b = 0; b < 8; b++) {
            ax[b] += ar[b] * xv.x;
            ay[b] += ar[b] * xv.y;
        }
    }
    // self-loop
    int mm = g_flags[1] ? 0 : (g_flags[2] ? 1 : 2);
    int keep;
    if (mm == 0)      keep = ((const unsigned char*)mask)[n];
    else if (mm == 1) keep = ((const int*)mask)[n];
    else              keep = ((const int*)mask)[2 * n];
    if (keep) {
        float2 xv = *(const float2*)(x + (size_t)n * 64 + 2 * lane);
        float ar[8];
        *(float4*)&ar[0] = att_s[32];
        *(float4*)&ar[4] = att_s[33];
#pragma unroll
        for (int b = 0; b < 8; b++) {
            ax[b] += ar[b] * xv.x;
            ay[b] += ar[b] * xv.y;
        }
    }
    // store: col k = b*64 + 2*lane (+1) -> half2 index b*32 + lane
    __half2* dst = (__half2*)g_Ahi + (size_t)n * 256 + lane;
#pragma unroll
    for (int b = 0; b < 8; b++)
        dst[b * 32] = __floats2half2_rn(ax[b], ay[b]);
}

// ---------------- K6: mma.sync fp16 GEMM, double-buffered, 2 CTAs/SM ------
#define OFF_B  0
#define OFF_A0 66560
#define OFF_A1 84992
#define SMEM_MM 103424

__global__ __launch_bounds__(256, 2) void gemm_mm_kernel(
    float* __restrict__ out, int N) {
    extern __shared__ __align__(16) char sm[];
    uint32_t sbase = smem_u32(sm);
    int tid = threadIdx.x, wid = tid >> 5, lid = tid & 31;
    int nb = blockIdx.x * 128;
    int warp_m = (wid & 3) * 32;
    int warp_n = (wid >> 2) * 32;

    // ---- stage B once: 64 rows x 512 k fp16 ----
#pragma unroll
    for (int t = 0; t < 8; t++) {
        int idx = t * 256 + tid;
        int row = idx >> 5;
        int cb = (idx & 31) * 32;
        *(uint4*)(sm + OFF_B + row * 1040 + cb) =
            *(const uint4*)((const char*)g_Bthi + row * 1024 + cb);
        *(uint4*)(sm + OFF_B + row * 1040 + cb + 16) =
            *(const uint4*)((const char*)g_Bthi + row * 1024 + cb + 16);
    }

    auto stageA = [&](int c, uint32_t offA) {
#pragma unroll
        for (int t = 0; t < 2; t++) {
            int idx = t * 256 + tid;
            int row = idx >> 2;
            int cb = (idx & 3) * 32;
            size_t gb = (size_t)(nb + row) * 1024 + (size_t)c * 128 + cb;
            cp16(sbase + offA + row * 144 + cb, (const char*)g_Ahi + gb);
            cp16(sbase + offA + row * 144 + cb + 16, (const char*)g_Ahi + gb + 16);
        }
        CP_COMMIT();
    };

    float acc[2][4][4];
#pragma unroll
    for (int mt = 0; mt < 2; mt++)
#pragma unroll
        for (int nt = 0; nt < 4; nt++)
#pragma unroll
            for (int q = 0; q < 4; q++) acc[mt][nt][q] = 0.f;

    uint32_t a_row0 = (uint32_t)(warp_m + (lid & 15));
    uint32_t a_kb = (uint32_t)(lid & 16);
    uint32_t a_off = a_row0 * 144 + a_kb;
    uint32_t b_row = (uint32_t)(warp_n + (lid & 7) + ((lid >> 4) & 1) * 8);
    uint32_t b_kb = (uint32_t)(((lid >> 3) & 1) * 16);
    uint32_t baddr0 = sbase + OFF_B + b_row * 1040 + b_kb;
    uint32_t baddr1 = baddr0 + 16 * 1040;

    stageA(0, OFF_A0);

    for (int c = 0; c < 8; c++) {
        int cur = c & 1;
        if (c < 7) stageA(c + 1, cur ? OFF_A0 : OFF_A1);
        if (c < 7) CP_WAIT(1); else CP_WAIT(0);
        __syncthreads();

        uint32_t ah0 = sbase + (cur ? OFF_A1 : OFF_A0) + a_off;

#pragma unroll
        for (int ks = 0; ks < 4; ks++) {
            uint32_t kb = (uint32_t)(ks * 32);
            uint32_t gkb = (uint32_t)(c * 128) + kb;
            uint32_t ahi[2][4];
            ldsm4(ahi[0], ah0 + kb);
            ldsm4(ahi[1], ah0 + 16 * 144 + kb);
            uint32_t bhp[2][4];
            ldsm4(bhp[0], baddr0 + gkb);
            ldsm4(bhp[1], baddr1 + gkb);
#pragma unroll
            for (int mt = 0; mt < 2; mt++) {
#pragma unroll
                for (int nt = 0; nt < 4; nt++) {
                    const uint32_t* bf = &bhp[nt >> 1][(nt & 1) * 2];
                    mma16816(acc[mt][nt], ahi[mt], bf);
                }
            }
        }
        __syncthreads();
    }

    int trow = lid >> 2, tcol = (lid & 3) * 2;
#pragma unroll
    for (int mt = 0; mt < 2; mt++) {
        int m0 = nb + warp_m + mt * 16 + trow;
#pragma unroll
        for (int nt = 0; nt < 4; nt++) {
            int col = warp_n + nt * 8 + tcol;
            if (m0 < N)
                *(float2*)(out + (size_t)m0 * 64 + col) =
                    make_float2(acc[mt][nt][0], acc[mt][nt][1]);
            if (m0 + 8 < N)
                *(float2*)(out + (size_t)(m0 + 8) * 64 + col) =
                    make_float2(acc[mt][nt][2], acc[mt][nt][3]);
        }
    }
}

// ---------------- launch ----------------
extern "C" void kernel_launch(void* const* d_in, const int* in_sizes, int n_in,
                              void* d_out, int out_size) {
    const float* x = (const float*)d_in[0];
    const void* mask = d_in[1];
    const int* src = (const int*)d_in[2];
    const int* tgt = (const int*)d_in[3];
    const int* et = (const int*)d_in[4];
    const float* bases = (const float*)d_in[5];
    const float* att = (const float*)d_in[6];
    float* out = (float*)d_out;

    int N = in_sizes[1];
    int E = in_sizes[2];
    int nb = (N + 1023) / 1024;

    cudaFuncSetAttribute(gemm_mm_kernel,
                         cudaFuncAttributeMaxDynamicSharedMemorySize, SMEM_MM);

    zero_kernel<<<256, 256>>>(N);
    sniff_kernel<<<256, 256>>>((const unsigned int*)d_in[2], E,
                               (const unsigned int*)d_in[1], N);
    prep_bases_kernel<<<128, 256>>>(bases);
    hist_kernel<<<3200, 256>>>(src, tgt, E);
    scan1_kernel<<<nb, 256>>>(N);
    scan2_kernel<<<1, 256>>>(nb, N);
    scan3_kernel<<<nb, 256>>>(N);
    scatter_kernel<<<3200, 256>>>(src, tgt, et, E);
    agg_kernel<<<(N + 7) / 8, 256>>>(x, mask, att, N);
    gemm_mm_kernel<<<(N + 127) / 128, 256, SMEM_MM>>>(out, N);
}

// round 13
// speedup vs baseline: 1.1696x; 1.0220x over previous
#include <cuda_runtime.h>
#include <cuda_fp16.h>
#include <cstdint>

#define NN 200000
#define NE 800000
#define NPAD 200064   // 1563 * 128

// ---------------- device scratch (no allocations allowed) ----------------
__device__ unsigned int g_flags[3];   // zero-init; OR-monotone, replay-safe
__device__ int g_count[NN];
__device__ int g_off[NN + 1];
__device__ int g_cur[NN];
__device__ int g_bsum[256];
__device__ int g_boff[256];
__device__ unsigned int g_sorted[2 * NE + 1];  // +1 pad for prefetch
__device__ __half g_Ahi[(size_t)NPAD * 512];   // 205 MB
__device__ __half g_Bthi[64 * 512];            // basesT fp16 (n-major)

// ---------------- helpers ----------------
__device__ __forceinline__ int ldidx(const int* p, int i, int is64) {
    return is64 ? p[2 * i] : p[i];
}
__device__ __forceinline__ uint32_t smem_u32(const void* p) {
    uint32_t a;
    asm("{ .reg .u64 t; cvta.to.shared.u64 t, %1; cvt.u32.u64 %0, t; }"
        : "=r"(a) : "l"(p));
    return a;
}
__device__ __forceinline__ void ldsm4(uint32_t* r, uint32_t addr) {
    asm volatile("ldmatrix.sync.aligned.m8n8.x4.shared.b16 {%0,%1,%2,%3}, [%4];"
                 : "=r"(r[0]), "=r"(r[1]), "=r"(r[2]), "=r"(r[3]) : "r"(addr));
}
__device__ __forceinline__ void mma16816(float* c, const uint32_t* a,
                                         const uint32_t* b) {
    asm volatile(
        "mma.sync.aligned.m16n8k16.row.col.f32.f16.f16.f32 "
        "{%0,%1,%2,%3}, {%4,%5,%6,%7}, {%8,%9}, {%0,%1,%2,%3};"
        : "+f"(c[0]), "+f"(c[1]), "+f"(c[2]), "+f"(c[3])
        : "r"(a[0]), "r"(a[1]), "r"(a[2]), "r"(a[3]), "r"(b[0]), "r"(b[1]));
}
__device__ __forceinline__ void cp16(uint32_t saddr, const void* gptr) {
    asm volatile("cp.async.cg.shared.global [%0], [%1], 16;"
                 :: "r"(saddr), "l"(gptr) : "memory");
}
#define CP_COMMIT() asm volatile("cp.async.commit_group;" ::: "memory")
#define CP_WAIT(n)  asm volatile("cp.async.wait_group %0;" :: "n"(n) : "memory")

// ---------------- K0a: zero hist ----------------
__global__ void zero_kernel(int N) {
    int i0 = blockIdx.x * blockDim.x + threadIdx.x;
    for (int i = i0; i < N; i += gridDim.x * blockDim.x) g_count[i] = 0;
}

// ---------------- K0b: parallel dtype sniff ----------------
__global__ void sniff_kernel(const unsigned int* idx_words, int n_idx_words,
                             const unsigned int* mask_words, int n_mask) {
    int i0 = blockIdx.x * blockDim.x + threadIdx.x;
    int stride = gridDim.x * blockDim.x;
    unsigned f0 = 0, f1 = 0, f2 = 0;
    for (int i = 1 + 2 * i0; i < n_idx_words; i += 2 * stride)
        f0 |= (idx_words[i] != 0u);
    for (int i = i0; i < n_mask / 4; i += stride)
        f1 |= (mask_words[i] > 1u);
    for (int i = 1 + 2 * i0; i < n_mask / 2; i += 2 * stride)
        f2 |= (mask_words[i] != 0u);
    if (f0) atomicOr(&g_flags[0], 1u);
    if (f1) atomicOr(&g_flags[1], 1u);
    if (f2) atomicOr(&g_flags[2], 1u);
}

// ---------------- prep: basesT to fp16 ----------------
__global__ void prep_bases_kernel(const float* __restrict__ bases) {
    for (int idx = blockIdx.x * blockDim.x + threadIdx.x; idx < 512 * 64;
         idx += gridDim.x * blockDim.x) {
        int n = idx >> 9, k = idx & 511;
        g_Bthi[n * 512 + k] = __float2half(bases[k * 64 + n]);
    }
}

// ---------------- K2: histogram of edge-direction targets ----------------
__global__ void hist_kernel(const int* src, const int* tgt, int E) {
    int is64 = g_flags[0] ? 0 : 1;
    for (int i = blockIdx.x * blockDim.x + threadIdx.x; i < 2 * E;
         i += gridDim.x * blockDim.x) {
        int t = (i < E) ? ldidx(tgt, i, is64) : ldidx(src, i - E, is64);
        atomicAdd(&g_count[t], 1);
    }
}

// ---------------- K3: multi-block exclusive scan ----------------
__global__ void scan1_kernel(int N) {
    __shared__ int red[256];
    int b = blockIdx.x, t = threadIdx.x;
    int base = b * 1024 + t * 4;
    int s = 0;
#pragma unroll
    for (int j = 0; j < 4; j++) {
        int idx = base + j;
        if (idx < N) s += g_count[idx];
    }
    red[t] = s;
    __syncthreads();
    for (int off = 128; off > 0; off >>= 1) {
        if (t < off) red[t] += red[t + off];
        __syncthreads();
    }
    if (t == 0) g_bsum[b] = red[0];
}

__global__ void scan2_kernel(int nb, int N) {
    __shared__ int ts[256];
    int t = threadIdx.x;
    int v = (t < nb) ? g_bsum[t] : 0;
    ts[t] = v;
    __syncthreads();
    for (int off = 1; off < 256; off <<= 1) {
        int u = (t >= off) ? ts[t - off] : 0;
        __syncthreads();
        ts[t] += u;
        __syncthreads();
    }
    if (t < nb) g_boff[t] = ts[t] - v;
    if (t == 255) g_off[N] = ts[255];
}

__global__ void scan3_kernel(int N) {
    __shared__ int ts[256];
    int b = blockIdx.x, t = threadIdx.x;
    int base = b * 1024 + t * 4;
    int c[4];
    int s = 0;
#pragma unroll
    for (int j = 0; j < 4; j++) {
        int idx = base + j;
        c[j] = (idx < N) ? g_count[idx] : 0;
        s += c[j];
    }
    ts[t] = s;
    __syncthreads();
    for (int off = 1; off < 256; off <<= 1) {
        int u = (t >= off) ? ts[t - off] : 0;
        __syncthreads();
        ts[t] += u;
        __syncthreads();
    }
    int run = ts[t] - s + g_boff[b];
#pragma unroll
    for (int j = 0; j < 4; j++) {
        int idx = base + j;
        if (idx < N) {
            g_off[idx] = run;
            g_cur[idx] = run;
            run += c[j];
        }
    }
}

// ---------------- K4: scatter edges sorted by target ----------------
__global__ void scatter_kernel(const int* src, const int* tgt, const int* et,
                               int E) {
    int is64 = g_flags[0] ? 0 : 1;
    for (int i = blockIdx.x * blockDim.x + threadIdx.x; i < 2 * E;
         i += gridDim.x * blockDim.x) {
        int e = (i < E) ? i : i - E;
        int s, t;
        if (i < E) { s = ldidx(src, e, is64); t = ldidx(tgt, e, is64); }
        else       { s = ldidx(tgt, e, is64); t = ldidx(src, e, is64); }
        int r = ldidx(et, e, is64);
        int pos = atomicAdd(&g_cur[t], 1);
        g_sorted[pos] = ((unsigned int)s << 4) | (unsigned int)r;
    }
}

// ---------------- K5: aggregation, warp per node, pipelined edge words ------
__global__ void agg_kernel(const float* __restrict__ x,
                           const void* __restrict__ mask,
                           const float* __restrict__ att, int N) {
    __shared__ __align__(16) float4 att_s[34];
    int tid = threadIdx.x;
    if (tid < 34) att_s[tid] = ((const float4*)att)[tid];
    __syncthreads();

    int warp = tid >> 5, lane = tid & 31;
    int n = blockIdx.x * 8 + warp;
    if (n >= N) return;

    float acc0[8], acc1[8];
#pragma unroll
    for (int b = 0; b < 8; b++) { acc0[b] = 0.f; acc1[b] = 0.f; }

    int beg = g_off[n], end = g_off[n + 1];
    unsigned int p = g_sorted[beg];   // safe: padded array
#pragma unroll 1
    for (int i = beg; i < end; i++) {
        unsigned int pn = g_sorted[i + 1];  // prefetch next edge word
        int s = (int)(p >> 4);
        int r = (int)(p & 15u);
        float x0 = x[s * 64 + lane];
        float x1 = x[s * 64 + 32 + lane];
        float ar[8];
        *(float4*)&ar[0] = att_s[r * 2];
        *(float4*)&ar[4] = att_s[r * 2 + 1];
#pragma unroll
        for (int b = 0; b < 8; b++) {
            acc0[b] += ar[b] * x0;
            acc1[b] += ar[b] * x1;
        }
        p = pn;
    }
    // self-loop
    int mm = g_flags[1] ? 0 : (g_flags[2] ? 1 : 2);
    int keep;
    if (mm == 0)      keep = ((const unsigned char*)mask)[n];
    else if (mm == 1) keep = ((const int*)mask)[n];
    else              keep = ((const int*)mask)[2 * n];
    if (keep) {
        float x0 = x[n * 64 + lane];
        float x1 = x[n * 64 + 32 + lane];
        float ar[8];
        *(float4*)&ar[0] = att_s[32];
        *(float4*)&ar[4] = att_s[33];
#pragma unroll
        for (int b = 0; b < 8; b++) {
            acc0[b] += ar[b] * x0;
            acc1[b] += ar[b] * x1;
        }
    }
    size_t base = (size_t)n * 512;
#pragma unroll
    for (int b = 0; b < 8; b++) {
        g_Ahi[base + b * 64 + lane]      = __float2half(acc0[b]);
        g_Ahi[base + b * 64 + 32 + lane] = __float2half(acc1[b]);
    }
}

// ---------------- K6: mma.sync fp16 GEMM, double-buffered, 2 CTAs/SM ------
#define OFF_B  0
#define OFF_A0 66560
#define OFF_A1 84992
#define SMEM_MM 103424

__global__ __launch_bounds__(256, 2) void gemm_mm_kernel(
    float* __restrict__ out, int N) {
    extern __shared__ __align__(16) char sm[];
    uint32_t sbase = smem_u32(sm);
    int tid = threadIdx.x, wid = tid >> 5, lid = tid & 31;
    int nb = blockIdx.x * 128;
    int warp_m = (wid & 3) * 32;
    int warp_n = (wid >> 2) * 32;

    // ---- stage B once: 64 rows x 512 k fp16 ----
#pragma unroll
    for (int t = 0; t < 8; t++) {
        int idx = t * 256 + tid;
        int row = idx >> 5;
        int cb = (idx & 31) * 32;
        *(uint4*)(sm + OFF_B + row * 1040 + cb) =
            *(const uint4*)((const char*)g_Bthi + row * 1024 + cb);
        *(uint4*)(sm + OFF_B + row * 1040 + cb + 16) =
            *(const uint4*)((const char*)g_Bthi + row * 1024 + cb + 16);
    }

    auto stageA = [&](int c, uint32_t offA) {
#pragma unroll
        for (int t = 0; t < 2; t++) {
            int idx = t * 256 + tid;
            int row = idx >> 2;
            int cb = (idx & 3) * 32;
            size_t gb = (size_t)(nb + row) * 1024 + (size_t)c * 128 + cb;
            cp16(sbase + offA + row * 144 + cb, (const char*)g_Ahi + gb);
            cp16(sbase + offA + row * 144 + cb + 16, (const char*)g_Ahi + gb + 16);
        }
        CP_COMMIT();
    };

    float acc[2][4][4];
#pragma unroll
    for (int mt = 0; mt < 2; mt++)
#pragma unroll
        for (int nt = 0; nt < 4; nt++)
#pragma unroll
            for (int q = 0; q < 4; q++) acc[mt][nt][q] = 0.f;

    uint32_t a_row0 = (uint32_t)(warp_m + (lid & 15));
    uint32_t a_kb = (uint32_t)(lid & 16);
    uint32_t a_off = a_row0 * 144 + a_kb;
    uint32_t b_row = (uint32_t)(warp_n + (lid & 7) + ((lid >> 4) & 1) * 8);
    uint32_t b_kb = (uint32_t)(((lid >> 3) & 1) * 16);
    uint32_t baddr0 = sbase + OFF_B + b_row * 1040 + b_kb;
    uint32_t baddr1 = baddr0 + 16 * 1040;

    stageA(0, OFF_A0);

    for (int c = 0; c < 8; c++) {
        int cur = c & 1;
        if (c < 7) stageA(c + 1, cur ? OFF_A0 : OFF_A1);
        if (c < 7) CP_WAIT(1); else CP_WAIT(0);
        __syncthreads();

        uint32_t ah0 = sbase + (cur ? OFF_A1 : OFF_A0) + a_off;

#pragma unroll
        for (int ks = 0; ks < 4; ks++) {
            uint32_t kb = (uint32_t)(ks * 32);
            uint32_t gkb = (uint32_t)(c * 128) + kb;
            uint32_t ahi[2][4];
            ldsm4(ahi[0], ah0 + kb);
            ldsm4(ahi[1], ah0 + 16 * 144 + kb);
            uint32_t bhp[2][4];
            ldsm4(bhp[0], baddr0 + gkb);
            ldsm4(bhp[1], baddr1 + gkb);
#pragma unroll
            for (int mt = 0; mt < 2; mt++) {
#pragma unroll
                for (int nt = 0; nt < 4; nt++) {
                    const uint32_t* bf = &bhp[nt >> 1][(nt & 1) * 2];
                    mma16816(acc[mt][nt], ahi[mt], bf);
                }
            }
        }
        __syncthreads();
    }

    int trow = lid >> 2, tcol = (lid & 3) * 2;
#pragma unroll
    for (int mt = 0; mt < 2; mt++) {
        int m0 = nb + warp_m + mt * 16 + trow;
#pragma unroll
        for (int nt = 0; nt < 4; nt++) {
            int col = warp_n + nt * 8 + tcol;
            if (m0 < N)
                *(float2*)(out + (size_t)m0 * 64 + col) =
                    make_float2(acc[mt][nt][0], acc[mt][nt][1]);
            if (m0 + 8 < N)
                *(float2*)(out + (size_t)(m0 + 8) * 64 + col) =
                    make_float2(acc[mt][nt][2], acc[mt][nt][3]);
        }
    }
}

// ---------------- launch ----------------
extern "C" void kernel_launch(void* const* d_in, const int* in_sizes, int n_in,
                              void* d_out, int out_size) {
    const float* x = (const float*)d_in[0];
    const void* mask = d_in[1];
    const int* src = (const int*)d_in[2];
    const int* tgt = (const int*)d_in[3];
    const int* et = (const int*)d_in[4];
    const float* bases = (const float*)d_in[5];
    const float* att = (const float*)d_in[6];
    float* out = (float*)d_out;

    int N = in_sizes[1];
    int E = in_sizes[2];
    int nb = (N + 1023) / 1024;

    cudaFuncSetAttribute(gemm_mm_kernel,
                         cudaFuncAttributeMaxDynamicSharedMemorySize, SMEM_MM);

    zero_kernel<<<256, 256>>>(N);
    sniff_kernel<<<256, 256>>>((const unsigned int*)d_in[2], E,
                               (const unsigned int*)d_in[1], N);
    prep_bases_kernel<<<128, 256>>>(bases);
    hist_kernel<<<3200, 256>>>(src, tgt, E);
    scan1_kernel<<<nb, 256>>>(N);
    scan2_kernel<<<1, 256>>>(nb, N);
    scan3_kernel<<<nb, 256>>>(N);
    scatter_kernel<<<3200, 256>>>(src, tgt, et, E);
    agg_kernel<<<(N + 7) / 8, 256>>>(x, mask, att, N);
    gemm_mm_kernel<<<(N + 127) / 128, 256, SMEM_MM>>>(out, N);
}